// round 1
// baseline (speedup 1.0000x reference)
#include <cuda_runtime.h>

#define B_   32
#define CI   64
#define CO   64
#define N_   4096
#define M1   1024      // modes1
#define K_   2049      // output length N/2+1
#define KPAD 2052      // padded cas row stride (mult of 4 for float4)
#define ROWS (B_*CI)   // 2048

// -------- device scratch (static globals; no allocation) --------
__device__ float g_tw[4096];                 // butterfly twiddles, offset h holds cas(2*pi*j/(2h))
__device__ float g_cas[M1 * KPAD + 256];     // idht cas matrix [k][n], padded
__device__ float g_wp[M1 * CI * CO];         // [k][i][o] = w[i,o,k] + w[CI-1-i,o,k]
__device__ float g_wm[M1 * CI * CO];         // [k][i][o] = w[i,o,k] - w[CI-1-i,o,k]
__device__ float g_xhT[M1 * ROWS];           // FHT output, k-major: [k][b*CI+ci]
__device__ float g_ohT[M1 * (B_*CO)];        // mixed modes, k-major: [k][b*CO+o]

#define TWO_PI_F 6.283185307179586f

// -------- twiddle table: g_tw[h + j] = cas(2*pi*j/(2h)), h = 1,2,...,2048 --------
__global__ void tw_kernel() {
    int t = blockIdx.x * blockDim.x + threadIdx.x;
    if (t < 1 || t >= 4096) return;
    int h = 1 << (31 - __clz(t));
    int j = t - h;
    float ang = (TWO_PI_F * (float)j) / (float)(2 * h);
    float s, c; sincosf(ang, &s, &c);
    g_tw[t] = c + s;
}

// -------- cas matrix for idht: cas[k][n] = cos(2*pi*k*n/2049) + sin(...) --------
__global__ void cas_kernel() {
    int idx = blockIdx.x * blockDim.x + threadIdx.x;
    if (idx >= M1 * KPAD) return;
    int k = idx / KPAD, n = idx % KPAD;
    // match jax f32 op order: fl(fl(2pi_f * (k*n)) / 2049)
    float ang = (TWO_PI_F * ((float)k * (float)n)) / 2049.0f;
    float s, c; sincosf(ang, &s, &c);
    g_cas[idx] = c + s;
}

// -------- fold + transpose weights: w[i][o][k] -> wp/wm[k][i][o] --------
__global__ void wpm_kernel(const float* __restrict__ w) {
    __shared__ float sp[32][33];
    __shared__ float sm[32][33];
    int i  = blockIdx.z;
    int o0 = blockIdx.y * 32;
    int k0 = blockIdx.x * 32;
    int tx = threadIdx.x, ty = threadIdx.y;
    size_t off1 = ((size_t)i          * CO + (o0 + ty)) * M1 + k0 + tx;
    size_t off2 = ((size_t)(CI - 1 - i) * CO + (o0 + ty)) * M1 + k0 + tx;
    float a = w[off1], b = w[off2];
    sp[ty][tx] = a + b;
    sm[ty][tx] = a - b;
    __syncthreads();
    size_t woff = (size_t)(k0 + ty) * (CI * CO) + (size_t)i * CO + (o0 + tx);
    g_wp[woff] = sp[tx][ty];
    g_wm[woff] = sm[tx][ty];
}

// -------- FHT: iterative DIT, exact op-tree match of the reference recursion --------
__global__ void __launch_bounds__(256) fht_kernel(const float* __restrict__ x) {
    __shared__ float s[N_];
    int row = blockIdx.x;                       // b*CI + ci
    const float* xr = x + (size_t)row * N_;
    for (int n = threadIdx.x; n < N_; n += 256)
        s[__brev((unsigned)n) >> 20] = xr[n];   // bit-reversed load (12-bit)
    __syncthreads();
    int sh = 0;
    for (int h = 1; h < N_; h <<= 1, sh++) {
        for (int t = threadIdx.x; t < N_ / 2; t += 256) {
            int j = t & (h - 1);
            int base = ((t >> sh) << (sh + 1)) + j;
            float tw = g_tw[h + j];
            float u = s[base], v = s[base + h];
            float tv = tw * v;
            s[base]     = u + tv;
            s[base + h] = u - tv;
        }
        __syncthreads();
    }
    // write first M1 modes, k-major (scattered, small volume)
    for (int k = threadIdx.x; k < M1; k += 256)
        g_xhT[(size_t)k * ROWS + row] = s[k];
}

// -------- mode mixing: per-k batched small GEMM (with batch-flip term) --------
__global__ void __launch_bounds__(256) mix_kernel() {
    int k = blockIdx.x;
    __shared__ float sX [ROWS];     // [b][i]
    __shared__ float sWp[CI * CO];  // [i][o]
    __shared__ float sWm[CI * CO];
    const float* Xk = g_xhT + (size_t)k * ROWS;
    const float* wp = g_wp  + (size_t)k * CI * CO;
    const float* wm = g_wm  + (size_t)k * CI * CO;
    for (int i = threadIdx.x; i < ROWS; i += 256) sX[i] = Xk[i];
    for (int i = threadIdx.x; i < CI * CO; i += 256) { sWp[i] = wp[i]; sWm[i] = wm[i]; }
    __syncthreads();
    int o  = threadIdx.x & 63;
    int bq = threadIdx.x >> 6;      // 0..3, each covers 8 batches
    float acc[8];
#pragma unroll
    for (int r = 0; r < 8; r++) acc[r] = 0.f;
    for (int i = 0; i < CI; i++) {
        float wpv = sWp[i * CO + o];
        float wmv = sWm[i * CO + o];
#pragma unroll
        for (int r = 0; r < 8; r++) {
            int b = bq * 8 + r;
            acc[r] += sX[b * CI + i] * wpv;
            acc[r] += sX[(B_ - 1 - b) * CI + i] * wmv;
        }
    }
    float* ok = g_ohT + (size_t)k * (B_ * CO);
#pragma unroll
    for (int r = 0; r < 8; r++)
        ok[(bq * 8 + r) * CO + o] = 0.5f * acc[r];
}

// -------- idht GEMM: out[m][n] = (1/2049) * sum_k ohT[k][m] * cas[k][n] --------
#define BM 128
#define BN 128
#define BK 8
__global__ void __launch_bounds__(256) gemm_kernel(float* __restrict__ out) {
    __shared__ float sA[BK][BM];
    __shared__ float sB[BK][BN];
    int m0 = blockIdx.y * BM;
    int n0 = blockIdx.x * BN;
    int tid = threadIdx.x;
    int tx = tid & 15, ty = tid >> 4;
    float acc[8][8];
#pragma unroll
    for (int i = 0; i < 8; i++)
#pragma unroll
        for (int j = 0; j < 8; j++) acc[i][j] = 0.f;

    const float* A  = g_ohT;   // [k][m], row stride ROWS
    const float* Bm = g_cas;   // [k][n], row stride KPAD

    for (int k0 = 0; k0 < M1; k0 += BK) {
        int r  = tid >> 5;           // 0..7 (k within tile)
        int c4 = (tid & 31) * 4;     // 0..124
        *(float4*)&sA[r][c4] = *(const float4*)(A  + (size_t)(k0 + r) * ROWS + m0 + c4);
        *(float4*)&sB[r][c4] = *(const float4*)(Bm + (size_t)(k0 + r) * KPAD + n0 + c4);
        __syncthreads();
#pragma unroll
        for (int kk = 0; kk < BK; kk++) {
            float af[8], bf[8];
            *(float4*)&af[0] = *(float4*)&sA[kk][ty * 8];
            *(float4*)&af[4] = *(float4*)&sA[kk][ty * 8 + 4];
            *(float4*)&bf[0] = *(float4*)&sB[kk][tx * 8];
            *(float4*)&bf[4] = *(float4*)&sB[kk][tx * 8 + 4];
#pragma unroll
            for (int ii = 0; ii < 8; ii++)
#pragma unroll
                for (int jj = 0; jj < 8; jj++)
                    acc[ii][jj] += af[ii] * bf[jj];
        }
        __syncthreads();
    }
#pragma unroll
    for (int ii = 0; ii < 8; ii++) {
        int m = m0 + ty * 8 + ii;
#pragma unroll
        for (int jj = 0; jj < 8; jj++) {
            int n = n0 + tx * 8 + jj;
            if (n < K_) out[(size_t)m * K_ + n] = acc[ii][jj] / 2049.0f;
        }
    }
}

extern "C" void kernel_launch(void* const* d_in, const int* in_sizes, int n_in,
                              void* d_out, int out_size) {
    const float* x = (const float*)d_in[0];
    const float* w = (const float*)d_in[1];
    float* out = (float*)d_out;

    tw_kernel<<<16, 256>>>();
    cas_kernel<<<(M1 * KPAD + 255) / 256, 256>>>();
    wpm_kernel<<<dim3(32, 2, 64), dim3(32, 32)>>>(w);
    fht_kernel<<<ROWS, 256>>>(x);
    mix_kernel<<<M1, 256>>>();
    gemm_kernel<<<dim3((K_ + BN - 1) / BN, ROWS / BM), 256>>>(out);
}

// round 4
// speedup vs baseline: 2.0702x; 2.0702x over previous
#include <cuda_runtime.h>
#include <cstdint>

#define B_   32
#define CI   64
#define CO   64
#define N_   4096
#define M1   1024      // modes1
#define K_   2049      // output length N/2+1
#define ROWS (B_*CI)   // 2048
#define NCAS 2304      // padded n rows for cas (9 * 256)

// -------- device scratch (static globals; no allocation) --------
__device__ float g_tw[4096];                 // butterfly twiddles: g_tw[h+j] = cas(2*pi*j/(2h))
__device__ float g_casP[NCAS * M1];          // idht cas, [n][k] PERMUTED to mma-frag order, tf32-rounded
__device__ float g_wp[M1 * CI * CO];         // [k][i][o] = w[i,o,k] + w[CI-1-i,o,k]
__device__ float g_wm[M1 * CI * CO];         // [k][i][o] = w[i,o,k] - w[CI-1-i,o,k]
__device__ float g_xhT[M1 * ROWS];           // FHT output, k-major: [k][b*CI+ci]
__device__ float g_ohT[M1 * (B_*CO)];        // mixed modes, k-major: [k][b*CO+o], tf32-rounded

#define TWO_PI_F 6.283185307179586f

__device__ __forceinline__ uint32_t f2tf32(float v) {
    uint32_t o;
    asm("cvt.rna.tf32.f32 %0, %1;" : "=r"(o) : "f"(v));
    return o;
}

// ================= setup kernels =================
__global__ void tw_kernel() {
    int t = blockIdx.x * blockDim.x + threadIdx.x;
    if (t < 1 || t >= 4096) return;
    int h = 1 << (31 - __clz(t));
    int j = t - h;
    float ang = (TWO_PI_F * (float)j) / (float)(2 * h);
    float s, c; sincosf(ang, &s, &c);
    g_tw[t] = c + s;
}

// cas in [n][P] with P the in-chunk fragment permutation:
// P = kc*32 + p,  p = sp*16? no: p bits: slot q = p>>2 (q = sp*4 + t), j = p&3
//   sp = p>>4, t = (p>>2)&3, j = p&3  ->  k = kc*32 + sp*16 + j*4 + t
__global__ void cas_kernel() {
    long idx = (long)blockIdx.x * blockDim.x + threadIdx.x;
    if (idx >= (long)NCAS * M1) return;
    int n = (int)(idx >> 10);
    int P = (int)(idx & 1023);
    int kc = P >> 5, p = P & 31;
    int k = kc * 32 + (p >> 4) * 16 + (p & 3) * 4 + ((p >> 2) & 3);
    float ang = (TWO_PI_F * ((float)k * (float)n)) / 2049.0f;
    float s, c; sincosf(ang, &s, &c);
    ((uint32_t*)g_casP)[idx] = f2tf32(c + s);
}

__global__ void wpm_kernel(const float* __restrict__ w) {
    __shared__ float sp[32][33];
    __shared__ float sm[32][33];
    int i  = blockIdx.z;
    int o0 = blockIdx.y * 32;
    int k0 = blockIdx.x * 32;
    int tx = threadIdx.x, ty = threadIdx.y;
    size_t off1 = ((size_t)i            * CO + (o0 + ty)) * M1 + k0 + tx;
    size_t off2 = ((size_t)(CI - 1 - i) * CO + (o0 + ty)) * M1 + k0 + tx;
    float a = w[off1], b = w[off2];
    sp[ty][tx] = a + b;
    sm[ty][tx] = a - b;
    __syncthreads();
    size_t woff = (size_t)(k0 + ty) * (CI * CO) + (size_t)i * CO + (o0 + tx);
    g_wp[woff] = sp[tx][ty];
    g_wm[woff] = sm[tx][ty];
}

// ================= FHT: 3-phase register-resident radix-16 =================
__global__ void __launch_bounds__(256) fht_kernel(const float* __restrict__ x) {
    __shared__ float s[N_ + N_ / 16];
    const int tid = threadIdx.x;
    const int row = blockIdx.x;
    const float* xr = x + (size_t)row * N_;

#pragma unroll
    for (int it = 0; it < 4; it++) {
        int n = tid * 4 + it * 1024;
        float4 v = *(const float4*)(xr + n);
        int p = n + (n >> 4);
        s[p] = v.x; s[p + 1] = v.y; s[p + 2] = v.z; s[p + 3] = v.w;
    }
    __syncthreads();

    float r[16];
    const int bt = __brev((unsigned)tid) >> 24;
#pragma unroll
    for (int q = 0; q < 16; q++) {
        int br = __brev((unsigned)q) >> 28;
        int idx = br * 256 + bt;
        r[q] = s[idx + (idx >> 4)];
    }
#pragma unroll
    for (int hs = 1; hs <= 8; hs <<= 1) {
#pragma unroll
        for (int q = 0; q < 16; q++) {
            if ((q & hs) == 0) {
                float tw = g_tw[hs + (q & (hs - 1))];
                float u = r[q], v = r[q + hs];
                float tv = tw * v;
                r[q] = u + tv; r[q + hs] = u - tv;
            }
        }
    }
    __syncthreads();
#pragma unroll
    for (int q = 0; q < 16; q++) {
        int idx = 16 * tid + q;
        s[idx + (idx >> 4)] = r[q];
    }
    __syncthreads();

    const int hi = tid >> 4, lo = tid & 15;
#pragma unroll
    for (int q = 0; q < 16; q++) {
        int idx = hi * 256 + q * 16 + lo;
        r[q] = s[idx + (idx >> 4)];
    }
#pragma unroll
    for (int hb = 1; hb <= 8; hb <<= 1) {
        int h = hb * 16;
#pragma unroll
        for (int q = 0; q < 16; q++) {
            if ((q & hb) == 0) {
                float tw = g_tw[h + (q & (hb - 1)) * 16 + lo];
                float u = r[q], v = r[q + hb];
                float tv = tw * v;
                r[q] = u + tv; r[q + hb] = u - tv;
            }
        }
    }
    __syncthreads();
#pragma unroll
    for (int q = 0; q < 16; q++) {
        int idx = hi * 256 + q * 16 + lo;
        s[idx + (idx >> 4)] = r[q];
    }
    __syncthreads();

#pragma unroll
    for (int q = 0; q < 16; q++) {
        int idx = q * 256 + tid;
        r[q] = s[idx + (idx >> 4)];
    }
#pragma unroll
    for (int hb = 1; hb <= 8; hb <<= 1) {
        int h = hb * 256;
#pragma unroll
        for (int q = 0; q < 16; q++) {
            if ((q & hb) == 0) {
                float tw = g_tw[h + (q & (hb - 1)) * 256 + tid];
                float u = r[q], v = r[q + hb];
                float tv = tw * v;
                r[q] = u + tv; r[q + hb] = u - tv;
            }
        }
    }
#pragma unroll
    for (int q = 0; q < 4; q++)
        g_xhT[(size_t)(q * 256 + tid) * ROWS + row] = r[q];
}

// ================= mode mixing =================
__global__ void __launch_bounds__(256) mix_kernel() {
    int k = blockIdx.x;
    __shared__ float sX [ROWS];
    __shared__ float sWp[CI * CO];
    __shared__ float sWm[CI * CO];
    const float* Xk = g_xhT + (size_t)k * ROWS;
    const float* wp = g_wp  + (size_t)k * CI * CO;
    const float* wm = g_wm  + (size_t)k * CI * CO;
    for (int i = threadIdx.x; i < ROWS; i += 256) sX[i] = Xk[i];
    for (int i = threadIdx.x; i < CI * CO; i += 256) { sWp[i] = wp[i]; sWm[i] = wm[i]; }
    __syncthreads();
    int o  = threadIdx.x & 63;
    int bq = threadIdx.x >> 6;
    float acc[8];
#pragma unroll
    for (int rr = 0; rr < 8; rr++) acc[rr] = 0.f;
    for (int i = 0; i < CI; i++) {
        float wpv = sWp[i * CO + o];
        float wmv = sWm[i * CO + o];
#pragma unroll
        for (int rr = 0; rr < 8; rr++) {
            int b = bq * 8 + rr;
            acc[rr] += sX[b * CI + i] * wpv;
            acc[rr] += sX[(B_ - 1 - b) * CI + i] * wmv;
        }
    }
    uint32_t* ok = (uint32_t*)(g_ohT + (size_t)k * (B_ * CO));
#pragma unroll
    for (int rr = 0; rr < 8; rr++)
        ok[(bq * 8 + rr) * CO + o] = f2tf32(0.5f * acc[rr]);
}

// ================= idht GEMM: mma.sync tf32 (sm_80+ portable) =================
// out[m][n] = (1/2049) * sum_k A[m][k] * B[n][k]
//   A[m][k] = g_ohT[k][m]  (k-major, transpose-staged to smem)
//   B[n][k] = g_casP[n][P] (pre-permuted fragment order)
#define GBM 128
#define GBN 256
#define GBK 32
#define GNCH (M1 / GBK)                   // 32
#define GEMM_SMEM (2*GBM*GBK*4 + 2*GBN*GBK*4)   // 32KB + 64KB = 96KB

__device__ __forceinline__ int swz(int r) { return ((r & 1) << 2) | ((r >> 1) & 3); }

#define MMA8(d, a0, a1, a2, a3, b0, b1) \
    asm volatile("mma.sync.aligned.m16n8k8.row.col.f32.tf32.tf32.f32 " \
        "{%0,%1,%2,%3}, {%4,%5,%6,%7}, {%8,%9}, {%0,%1,%2,%3};" \
        : "+f"((d)[0]), "+f"((d)[1]), "+f"((d)[2]), "+f"((d)[3]) \
        : "r"(a0), "r"(a1), "r"(a2), "r"(a3), "r"(b0), "r"(b1))

__global__ void __launch_bounds__(256, 1) gemm_kernel(float* __restrict__ out) {
    extern __shared__ float smem[];
    float* sA[2] = { smem,               smem + GBM * GBK };
    float* sB[2] = { smem + 2*GBM*GBK,   smem + 2*GBM*GBK + GBN * GBK };

    const int tid  = threadIdx.x;
    const int wid  = tid >> 5;
    const int lane = tid & 31;
    const int g    = lane >> 2;        // fragment group (row)
    const int t    = lane & 3;         // fragment thread-in-group (k)
    const int wm   = wid & 1;          // warp M index (0..1)
    const int wn   = wid >> 1;         // warp N index (0..3)
    const int m0   = blockIdx.y * GBM;
    const int n0   = blockIdx.x * GBN;

    // ---- staging maps ----
    // A: thread -> (m = tid&127, sp = tid>>7); 16 scalar LDG (coalesced over m), 4 STS.128
    const int smA = tid & 127;
    const int spA = tid >> 7;
    // B: thread -> (q = tid&7, nr = tid>>3); 8x (LDG.128 + STS.128)
    const int qB  = tid & 7;
    const int nrB = tid >> 3;

    const float* Ag = g_ohT + m0;                        // [k][m]
    const float* Bg = g_casP + (size_t)n0 * M1;          // [n][P]

    float acc[4][8][4];
#pragma unroll
    for (int a = 0; a < 4; a++)
#pragma unroll
        for (int b = 0; b < 8; b++)
#pragma unroll
            for (int c = 0; c < 4; c++) acc[a][b][c] = 0.f;

    float  ra[16];
    float4 rb[8];

    // prefetch chunk 0
#pragma unroll
    for (int tt = 0; tt < 4; tt++)
#pragma unroll
        for (int j = 0; j < 4; j++)
            ra[tt * 4 + j] = Ag[(size_t)(spA * 16 + 4 * j + tt) * ROWS + smA];
#pragma unroll
    for (int it = 0; it < 8; it++)
        rb[it] = *(const float4*)(Bg + (size_t)(nrB + 32 * it) * M1 + qB * 4);

    for (int c = 0; c < GNCH; c++) {
        const int bsel = c & 1;
        float* Ab = sA[bsel];
        float* Bb = sB[bsel];
        // ---- STS staged regs (conflict-free swizzled) ----
#pragma unroll
        for (int tt = 0; tt < 4; tt++) {
            float4 v = make_float4(__uint_as_float(f2tf32(ra[tt*4+0])),
                                   __uint_as_float(f2tf32(ra[tt*4+1])),
                                   __uint_as_float(f2tf32(ra[tt*4+2])),
                                   __uint_as_float(f2tf32(ra[tt*4+3])));
            int slot = (spA * 4 + tt) ^ swz(smA);
            *(float4*)(Ab + smA * 32 + slot * 4) = v;
        }
#pragma unroll
        for (int it = 0; it < 8; it++) {
            int n = nrB + 32 * it;
            int slot = qB ^ swz(n);
            *(float4*)(Bb + n * 32 + slot * 4) = rb[it];
        }
        // ---- prefetch chunk c+1 ----
        if (c + 1 < GNCH) {
            const int kb = (c + 1) * GBK;
#pragma unroll
            for (int tt = 0; tt < 4; tt++)
#pragma unroll
                for (int j = 0; j < 4; j++)
                    ra[tt * 4 + j] = Ag[(size_t)(kb + spA * 16 + 4 * j + tt) * ROWS + smA];
#pragma unroll
            for (int it = 0; it < 8; it++)
                rb[it] = *(const float4*)(Bg + (size_t)(nrB + 32 * it) * M1 + kb + qB * 4);
        }
        __syncthreads();
        // ---- MMA over buffer bsel ----
#pragma unroll
        for (int sp = 0; sp < 2; sp++) {
            uint4 bf[8];
#pragma unroll
            for (int nt = 0; nt < 8; nt++) {
                int row = wn * 64 + nt * 8 + g;
                int slot = (sp * 4 + t) ^ swz(row);
                bf[nt] = *(const uint4*)(Bb + row * 32 + slot * 4);
            }
#pragma unroll
            for (int mt = 0; mt < 4; mt++) {
                int rowa = wm * 64 + mt * 16 + g;
                int slot = (sp * 4 + t) ^ swz(rowa);          // swz(rowa+8) == swz(rowa)
                uint4 alo = *(const uint4*)(Ab + rowa * 32 + slot * 4);
                uint4 ahi = *(const uint4*)(Ab + (rowa + 8) * 32 + slot * 4);
#pragma unroll
                for (int nt = 0; nt < 8; nt++) {
                    MMA8(acc[mt][nt], alo.x, ahi.x, alo.y, ahi.y, bf[nt].x, bf[nt].y);
                    MMA8(acc[mt][nt], alo.z, ahi.z, alo.w, ahi.w, bf[nt].z, bf[nt].w);
                }
            }
        }
        // next iter's STS targets the other buffer; its hazard partner (MMA c-1)
        // is fenced by this loop's single __syncthreads.
    }

    // ---- epilogue ----
    const float inv = 1.0f / 2049.0f;
#pragma unroll
    for (int mt = 0; mt < 4; mt++) {
        int row = m0 + wm * 64 + mt * 16 + g;
#pragma unroll
        for (int nt = 0; nt < 8; nt++) {
            int col = n0 + wn * 64 + nt * 8 + t * 2;
            if (col < K_) {
                float* p0 = out + (size_t)row * K_ + col;
                float* p1 = out + (size_t)(row + 8) * K_ + col;
                p0[0] = acc[mt][nt][0] * inv;
                p1[0] = acc[mt][nt][2] * inv;
                if (col + 1 < K_) {
                    p0[1] = acc[mt][nt][1] * inv;
                    p1[1] = acc[mt][nt][3] * inv;
                }
            }
        }
    }
}

// ================= launch =================
extern "C" void kernel_launch(void* const* d_in, const int* in_sizes, int n_in,
                              void* d_out, int out_size) {
    const float* x = (const float*)d_in[0];
    const float* w = (const float*)d_in[1];
    float* out = (float*)d_out;

    cudaFuncSetAttribute(gemm_kernel, cudaFuncAttributeMaxDynamicSharedMemorySize, GEMM_SMEM);

    tw_kernel<<<16, 256>>>();
    cas_kernel<<<(NCAS * M1 + 255) / 256, 256>>>();
    wpm_kernel<<<dim3(32, 2, 64), dim3(32, 32)>>>(w);
    fht_kernel<<<ROWS, 256>>>(x);
    mix_kernel<<<M1, 256>>>();
    gemm_kernel<<<dim3(NCAS / GBN, ROWS / GBM), 256, GEMM_SMEM>>>(out);
}